// round 17
// baseline (speedup 1.0000x reference)
#include <cuda_runtime.h>
#include <cuda_bf16.h>

// Problem collapses analytically:
//   - quantum_expectation ≡ 0 (uniform state invariant under RX up to global
//     phase; CX chain is a permutation) -> p1 = 0.5, 2*p1-1 = 0 exactly.
//   - output = 0.5 * mean(sigmoid(conv2d_valid_4x4(data, w) + b)).
//
// R15 post-mortem: occ 61% but dur flat; launch_bounds(256,6) made 2 waves,
// and the partials->last-CTA tail is a fixed ~1us addend.
// R16: launch_bounds(256,8) (2048 thr/SM, single wave; weights via smem to
// fit ~32 regs) + deterministic fixed-point u64 atomic global sum (one
// atomic per warp; integer order-invariant) -> minimal serial tail.

#define IMGS        256
#define IMG_W       64
#define IMG_H       64
#define OUT_W       61               // 64 - 4 + 1
#define OUT_H       61
#define OUT_PER_IMG (OUT_W * OUT_H)  // 3721
#define BANDS       4
#define BAND_ROWS   16               // output rows per band (last band: 13)
#define NBLOCKS     (IMGS * BANDS)   // 1024
#define NTHREADS    256
#define NWARPS      (NTHREADS / 32)
#define FP_SCALE    4294967296.0     // 2^32

__device__ unsigned long long g_sum    = 0ULL;
__device__ unsigned int       g_ticket = 0;

__global__ __launch_bounds__(NTHREADS, 8)
void conv_hybrid_fused_kernel(const float* __restrict__ data,
                              const float* __restrict__ conv_w,
                              const float* __restrict__ conv_b,
                              float* __restrict__ out, int out_size)
{
    __shared__ float wsh[16];
    __shared__ float final_v;
    __shared__ bool  is_last;

    const int blk  = blockIdx.x;
    const int img  = blk >> 2;           // blk / BANDS
    const int band = blk & 3;            // blk % BANDS
    const int tid  = threadIdx.x;
    const int lane = tid & 31;

    if (tid < 16) wsh[tid] = conv_w[tid];
    const float bias = conv_b[0];
    __syncthreads();

    const int r0    = band * BAND_ROWS;
    const int nrows = (band < 3) ? BAND_ROWS : (OUT_H - 3 * BAND_ROWS); // 16/13

    // Thread -> (local row, 4-col segment): lrow = tid/16, cbase = 4*(tid%16).
    const int lrow  = tid >> 4;          // 0..15
    const int cbase = (tid & 15) << 2;   // 0,4,...,60

    float acc = 0.0f;
    if (lrow < nrows) {
        const float* __restrict__ base =
            data + (size_t)img * (IMG_H * IMG_W) + (size_t)(r0 + lrow) * IMG_W;
        // Second float4 covers cols cbase+4..cbase+7; for cbase==60 clamp to
        // 56 (stays in-row/in-bounds). Clamped values only feed outputs
        // 61..63, which are clipped below; output 60 uses cols 60..63 only.
        const int c2 = (cbase == 60) ? 56 : cbase + 4;

        // Streaming conv: per kernel-row 2 coalesced LDG.128 + 4 broadcast
        // LDS for the weights, folded into 4 accumulators.
        float s0 = bias, s1 = bias, s2 = bias, s3 = bias;
        #pragma unroll
        for (int ky = 0; ky < 4; ky++) {
            const float4 a = *reinterpret_cast<const float4*>(base + ky * IMG_W + cbase);
            const float4 b = *reinterpret_cast<const float4*>(base + ky * IMG_W + c2);
            const float w0 = wsh[ky * 4 + 0], w1 = wsh[ky * 4 + 1];
            const float w2 = wsh[ky * 4 + 2], w3 = wsh[ky * 4 + 3];
            s0 = fmaf(a.x, w0, s0); s0 = fmaf(a.y, w1, s0);
            s0 = fmaf(a.z, w2, s0); s0 = fmaf(a.w, w3, s0);
            s1 = fmaf(a.y, w0, s1); s1 = fmaf(a.z, w1, s1);
            s1 = fmaf(a.w, w2, s1); s1 = fmaf(b.x, w3, s1);
            s2 = fmaf(a.z, w0, s2); s2 = fmaf(a.w, w1, s2);
            s2 = fmaf(b.x, w2, s2); s2 = fmaf(b.y, w3, s2);
            s3 = fmaf(a.w, w0, s3); s3 = fmaf(b.x, w1, s3);
            s3 = fmaf(b.y, w2, s3); s3 = fmaf(b.z, w3, s3);
        }

        acc  = 1.0f / (1.0f + __expf(-s0));            // col cbase (<61 always)
        if (cbase + 1 < OUT_W) acc += 1.0f / (1.0f + __expf(-s1));
        if (cbase + 2 < OUT_W) acc += 1.0f / (1.0f + __expf(-s2));
        if (cbase + 3 < OUT_W) acc += 1.0f / (1.0f + __expf(-s3));
    }

    // Warp shfl reduction (fixed order -> deterministic).
    #pragma unroll
    for (int off = 16; off > 0; off >>= 1)
        acc += __shfl_down_sync(0xFFFFFFFFu, acc, off);

    // One u64 fixed-point atomic per warp. Integer addition is order-
    // invariant -> global sum fully deterministic. warp_sum < 128, scaled
    // < 2^39; 8192 warps -> total < 2^52, no overflow.
    if (lane == 0) {
        unsigned long long inc =
            (unsigned long long)((double)acc * FP_SCALE + 0.5);
        atomicAdd(&g_sum, inc);
        __threadfence();                 // order my add before the ticket
    }
    __syncthreads();

    if (tid == 0) {
        // Wraps to 0 after NBLOCKS-1 -> replay-safe under graph capture.
        unsigned int old = atomicInc(&g_ticket, NBLOCKS - 1);
        is_last = (old == NBLOCKS - 1);
    }
    __syncthreads();

    if (!is_last) return;

    // Last CTA: one coherent read of the total, compute, reset, broadcast.
    if (tid == 0) {
        unsigned long long total = atomicAdd(&g_sum, 0ULL);   // L2-coherent read
        final_v = (float)(0.5 * ((double)total / FP_SCALE
                                 / (double)(IMGS * OUT_PER_IMG)));
        atomicExch(&g_sum, 0ULL);        // last actor resets for next replay
    }
    __syncthreads();

    const float v = final_v;
    for (int i = tid; i < out_size; i += NTHREADS)
        out[i] = v;
}

extern "C" void kernel_launch(void* const* d_in, const int* in_sizes, int n_in,
                              void* d_out, int out_size)
{
    const float* data   = (const float*)d_in[0];   // 256*1*64*64
    const float* conv_w = (const float*)d_in[1];   // 16
    const float* conv_b = (const float*)d_in[2];   // 1
    float* out = (float*)d_out;

    conv_hybrid_fused_kernel<<<NBLOCKS, NTHREADS>>>(data, conv_w, conv_b, out, out_size);
}